// round 7
// baseline (speedup 1.0000x reference)
#include <cuda_runtime.h>
#include <cuda_fp16.h>
#include <cuda_bf16.h>

#define NN   50
#define NN2  2500          // N*N
#define ATT  4000          // alpha steps / t-range
#define BB   512           // batch
#define PP   32            // features p
#define NP   (BB * PP)     // 16384 (b,p) pairs
#define CAP  32            // per-t slot capacity (P(overflow) ~ 1e-18)

// Scratch (static __device__ globals: allocation-free rule)
__device__ float  g_F[NN2];                   // F = g @ w^2
__device__ __half g_fT[(size_t)ATT * NN2];    // fT[t][j][i] in fp16 (20 MB)
__device__ int    g_cnt[ATT];                 // per-t pair count (ticket counter)
__device__ int    g_slot[ATT * CAP];          // pair indices per t
__device__ float  g_xT[(size_t)BB * PP * NN]; // xT[b][p][i] (i contiguous)

// ---------------------------------------------------------------------------
// Kernel A (grid 1250 x 256): 2 rows per block, 128 threads per row.
// Loads hand-batched (4 unconditional + 1 predicated float4 per thread) so
// all g-row LDG.128s are in flight together (MLP~5, DRAM-bandwidth-bound).
// Folds in: Z init, g_cnt zero, coalesced smem-tile x->xT transpose.
// ---------------------------------------------------------------------------
__global__ void kA_F(const float* __restrict__ g, const float* __restrict__ w,
                     float* __restrict__ outF,
                     const int* __restrict__ y_i, const float* __restrict__ mus,
                     const float* __restrict__ x, float* __restrict__ Z) {
    int gid = blockIdx.x * 256 + threadIdx.x;   // 320000 threads

    if (gid < BB * NN) {
        int b = gid / NN, i = gid - b * NN;
        Z[gid] = (float)PP * mus[(size_t)y_i[b] * NN + i];
    } else if (gid < BB * NN + ATT) {
        g_cnt[gid - BB * NN] = 0;
    }

    // Coalesced transpose: block b (<512) moves x[b][50][32] -> xT[b][32][50]
    __shared__ float tile[NN * PP];     // 1600 floats
    if (blockIdx.x < BB) {
        int b = blockIdx.x;
        const float* src = x + (size_t)b * (NN * PP);
        for (int o = threadIdx.x; o < NN * PP; o += 256)
            tile[o] = src[o];                       // coalesced (p fastest)
        __syncthreads();
        float* dst = g_xT + (size_t)b * (PP * NN);
        for (int o = threadIdx.x; o < PP * NN; o += 256) {
            int p = o / NN, i = o - p * NN;
            dst[o] = tile[i * PP + p];              // coalesced writes
        }
    }

    // Matvec: row = 2*blockIdx + (tid>=128); 128 threads per row; 625 float4.
    int half = threadIdx.x >> 7;            // 0 or 1
    int lt   = threadIdx.x & 127;
    int row  = blockIdx.x * 2 + half;
    if (row >= NN2) return;

    const float4* grow = (const float4*)(g + (size_t)row * NN2);
    const float4* w4   = (const float4*)w;
    bool p4 = (lt < 625 - 512);             // lt < 113

    // Batched independent loads (front-issued by ptxas)
    float4 g0 = grow[lt];
    float4 g1 = grow[lt + 128];
    float4 g2 = grow[lt + 256];
    float4 g3 = grow[lt + 384];
    float4 g4 = p4 ? grow[lt + 512] : make_float4(0.f, 0.f, 0.f, 0.f);
    float4 w0 = w4[lt];
    float4 w1 = w4[lt + 128];
    float4 w2 = w4[lt + 256];
    float4 w3 = w4[lt + 384];
    float4 w5 = p4 ? w4[lt + 512] : make_float4(0.f, 0.f, 0.f, 0.f);

    float s = 0.f;
    s += g0.x*(w0.x*w0.x) + g0.y*(w0.y*w0.y) + g0.z*(w0.z*w0.z) + g0.w*(w0.w*w0.w);
    s += g1.x*(w1.x*w1.x) + g1.y*(w1.y*w1.y) + g1.z*(w1.z*w1.z) + g1.w*(w1.w*w1.w);
    s += g2.x*(w2.x*w2.x) + g2.y*(w2.y*w2.y) + g2.z*(w2.z*w2.z) + g2.w*(w2.w*w2.w);
    s += g3.x*(w3.x*w3.x) + g3.y*(w3.y*w3.y) + g3.z*(w3.z*w3.z) + g3.w*(w3.w*w3.w);
    s += g4.x*(w5.x*w5.x) + g4.y*(w5.y*w5.y) + g4.z*(w5.z*w5.z) + g4.w*(w5.w*w5.w);

    #pragma unroll
    for (int o = 16; o; o >>= 1) s += __shfl_down_sync(0xffffffffu, s, o);

    __shared__ float red[2][4];
    int lane = threadIdx.x & 31, wid = (threadIdx.x >> 5) & 3;
    if (lane == 0) red[half][wid] = s;
    __syncthreads();
    if (wid == 0 && lane == 0) {
        float r = red[half][0] + red[half][1] + red[half][2] + red[half][3];
        g_F[row] = r; outF[row] = r;
    }
}

// ---------------------------------------------------------------------------
// Kernel B (grid 1000 x 256): softmax table (fp16 stores), 4 t per block.
// Folds in hist+scatter: ticket = atomicAdd(cnt[t]) doubles as slot index.
// ---------------------------------------------------------------------------
__global__ void kB_softmaxT(const float* __restrict__ alphas,
                            const int* __restrict__ x_i) {
    int gid = blockIdx.x * 256 + threadIdx.x;
    if (gid < NP) {
        int t = x_i[gid];
        int ticket = atomicAdd(&g_cnt[t], 1);
        if (ticket < CAP) g_slot[t * CAP + ticket] = gid;
    }

    __shared__ float Fs[NN2];
    for (int idx = threadIdx.x; idx < NN2; idx += 256)
        Fs[idx] = g_F[idx];
    __syncthreads();

    int lt = threadIdx.x >> 6;        // 0..3
    int i  = threadIdx.x & 63;        // row index
    int t  = (blockIdx.x << 2) + lt;
    if (i >= NN) return;

    float a = alphas[t];
    float e[NN];
    float s = 0.f;
    #pragma unroll
    for (int j = 0; j < NN; j++) {
        float v = __expf(-a * Fs[i * NN + j]);
        e[j] = v;
        s += v;
    }
    float rinv = __fdividef(1.0f, s);
    __half* dst = g_fT + (size_t)t * NN2 + i;
    #pragma unroll
    for (int j = 0; j < NN; j++)
        dst[j * NN] = __float2half_rn(e[j] * rinv);
}

// ---------------------------------------------------------------------------
// Kernel C2 (grid 4000 x 64): one block per t. Loads fT[t] row into registers
// ONCE (thread i holds f[i][0..49], fp16->fp32) and applies it to all pairs
// with this t, 4 pairs per pass from smem.
// ---------------------------------------------------------------------------
__global__ void kC2(const float* __restrict__ mus, float* __restrict__ Z) {
    int t = blockIdx.x;
    int cnt = g_cnt[t];
    if (cnt == 0) return;
    if (cnt > CAP) cnt = CAP;

    int i = threadIdx.x;              // 0..63, active < 50
    __shared__ float a_s[4][NN + 2];

    float freg[NN];
    float mu_i = 0.f;
    if (i < NN) {
        mu_i = mus[(size_t)t * NN + i];
        const __half* fr = g_fT + (size_t)t * NN2 + i;
        #pragma unroll
        for (int j = 0; j < NN; j++) freg[j] = __half2float(fr[j * NN]);
    }

    for (int base = 0; base < cnt; base += 4) {
        if (i < NN) {
            #pragma unroll
            for (int k = 0; k < 4; k++) {
                int q = base + k;
                int pr = (q < cnt) ? g_slot[t * CAP + q] : 0;
                a_s[k][i] = g_xT[(size_t)pr * NN + i] - mu_i;
            }
        }
        __syncthreads();
        if (i < NN) {
            float acc0 = 0.f, acc1 = 0.f, acc2 = 0.f, acc3 = 0.f;
            #pragma unroll
            for (int j = 0; j < NN; j++) {
                float f = freg[j];
                acc0 += f * a_s[0][j];
                acc1 += f * a_s[1][j];
                acc2 += f * a_s[2][j];
                acc3 += f * a_s[3][j];
            }
            float acc[4] = {acc0, acc1, acc2, acc3};
            #pragma unroll
            for (int k = 0; k < 4; k++) {
                int q = base + k;
                if (q < cnt) {
                    int pr = g_slot[t * CAP + q];
                    int b = pr >> 5;
                    atomicAdd(&Z[b * NN + i], acc[k]);
                }
            }
        }
        __syncthreads();
    }
}

// ---------------------------------------------------------------------------
extern "C" void kernel_launch(void* const* d_in, const int* in_sizes, int n_in,
                              void* d_out, int out_size) {
    const float* x      = (const float*)d_in[0];   // [512,50,32]
    const int*   x_i    = (const int*)  d_in[1];   // [512,32]
    const int*   y_i    = (const int*)  d_in[2];   // [512]
    const float* g      = (const float*)d_in[3];   // [2500,2500]
    const float* w      = (const float*)d_in[4];   // [2500,1]
    const float* mus    = (const float*)d_in[5];   // [4000,50]
    const float* alphas = (const float*)d_in[6];   // [4000,1]

    float* Z    = (float*)d_out;        // [512*50]
    float* outF = Z + BB * NN;          // [2500]

    kA_F<<<1250, 256>>>(g, w, outF, y_i, mus, x, Z);
    kB_softmaxT<<<ATT / 4, 256>>>(alphas, x_i);
    kC2<<<ATT, 64>>>(mus, Z);
}

// round 8
// speedup vs baseline: 1.3643x; 1.3643x over previous
#include <cuda_runtime.h>
#include <cuda_bf16.h>

#define NN   50
#define NN2  2500          // N*N
#define ATT  4000          // alpha steps / t-range
#define BB   512           // batch
#define PP   32            // features p
#define NP   (BB * PP)     // 16384 (b,p) pairs
#define CAP  32            // per-t slot capacity (P(overflow) ~ 1e-18)

// Scratch (static __device__ globals: allocation-free rule)
__device__ float g_F[NN2];                   // F = g @ w^2
__device__ float g_fT[(size_t)ATT * NN2];    // fT[t][j][i] (i fastest, 50-wide)
__device__ int   g_cnt[ATT];                 // per-t pair count (ticket counter)
__device__ int   g_slot[ATT * CAP];          // pair indices per t
__device__ float g_xT[(size_t)BB * PP * NN]; // xT[b][p][i] (i contiguous)

// ---------------------------------------------------------------------------
// Kernel A (grid 2500 x 256): block-per-row matvec with w^2 staged in smem.
// Each thread issues 2-3 independent g float4 LDGs (the only DRAM stream);
// w is read once per block (L2-hit) into smem, so no redundant-g/w L1 thrash.
// Folds in: Z init, g_cnt zero, coalesced smem-tile x->xT transpose (blocks<512).
// ---------------------------------------------------------------------------
__global__ void kA_F(const float* __restrict__ g, const float* __restrict__ w,
                     float* __restrict__ outF,
                     const int* __restrict__ y_i, const float* __restrict__ mus,
                     const float* __restrict__ x, float* __restrict__ Z) {
    int tid = threadIdx.x;
    int gid = blockIdx.x * 256 + tid;

    if (gid < BB * NN) {
        int b = gid / NN, i = gid - b * NN;
        Z[gid] = (float)PP * mus[(size_t)y_i[b] * NN + i];
    } else if (gid < BB * NN + ATT) {
        g_cnt[gid - BB * NN] = 0;
    }

    __shared__ float4 w2s[640];          // 625 used (10 KB)
    __shared__ float  tile[NN * PP];     // 1600 floats (6.4 KB)
    __shared__ float  red[8];

    // Stage w^2 (coalesced float4; L2-resident after first wave)
    const float4* w4 = (const float4*)w;
    for (int c = tid; c < NN2 / 4 + 1; c += 256) {
        if (c < NN2 / 4) {
            float4 wv = w4[c];
            w2s[c] = make_float4(wv.x * wv.x, wv.y * wv.y, wv.z * wv.z, wv.w * wv.w);
        }
    }

    // Transpose read phase: block b (<512) loads x[b][50][32]
    if (blockIdx.x < BB) {
        const float* src = x + (size_t)blockIdx.x * (NN * PP);
        for (int o = tid; o < NN * PP; o += 256)
            tile[o] = src[o];                       // coalesced (p fastest)
    }
    __syncthreads();

    // Transpose write phase
    if (blockIdx.x < BB) {
        float* dst = g_xT + (size_t)blockIdx.x * (PP * NN);
        for (int o = tid; o < PP * NN; o += 256) {
            int p = o / NN, i = o - p * NN;
            dst[o] = tile[i * PP + p];              // coalesced writes
        }
    }

    // Matvec: row = blockIdx.x; 625 float4, thread tid owns tid, tid+256, tid+512
    int row = blockIdx.x;
    const float4* grow = (const float4*)(g + (size_t)row * NN2);
    bool p2 = (tid < 625 - 512);                    // tid < 113

    float4 g0 = grow[tid];
    float4 g1 = grow[tid + 256];
    float4 g2 = p2 ? grow[tid + 512] : make_float4(0.f, 0.f, 0.f, 0.f);
    float4 w0 = w2s[tid];
    float4 w1 = w2s[tid + 256];
    float4 w2 = p2 ? w2s[tid + 512] : make_float4(0.f, 0.f, 0.f, 0.f);

    float s;
    s  = g0.x * w0.x + g0.y * w0.y + g0.z * w0.z + g0.w * w0.w;
    s += g1.x * w1.x + g1.y * w1.y + g1.z * w1.z + g1.w * w1.w;
    s += g2.x * w2.x + g2.y * w2.y + g2.z * w2.z + g2.w * w2.w;

    #pragma unroll
    for (int o = 16; o; o >>= 1) s += __shfl_down_sync(0xffffffffu, s, o);
    int lane = tid & 31, wid = tid >> 5;
    if (lane == 0) red[wid] = s;
    __syncthreads();
    if (wid == 0) {
        s = (lane < 8) ? red[lane] : 0.f;
        #pragma unroll
        for (int o = 4; o; o >>= 1) s += __shfl_down_sync(0xffffffffu, s, o);
        if (lane == 0) { g_F[row] = s; outF[row] = s; }
    }
}

// ---------------------------------------------------------------------------
// Kernel B (grid 1000 x 256): softmax table, 4 t per block, 64 threads per t.
// Folds in hist+scatter: ticket = atomicAdd(cnt[t]) doubles as slot index.
// ---------------------------------------------------------------------------
__global__ void kB_softmaxT(const float* __restrict__ alphas,
                            const int* __restrict__ x_i) {
    int gid = blockIdx.x * 256 + threadIdx.x;
    if (gid < NP) {
        int t = x_i[gid];
        int ticket = atomicAdd(&g_cnt[t], 1);
        if (ticket < CAP) g_slot[t * CAP + ticket] = gid;
    }

    __shared__ float Fs[NN2];
    for (int idx = threadIdx.x; idx < NN2; idx += 256)
        Fs[idx] = g_F[idx];
    __syncthreads();

    int lt = threadIdx.x >> 6;        // 0..3
    int i  = threadIdx.x & 63;        // row index
    int t  = (blockIdx.x << 2) + lt;
    if (i >= NN) return;

    float a = alphas[t];
    float e[NN];
    float s = 0.f;
    #pragma unroll
    for (int j = 0; j < NN; j++) {
        float v = __expf(-a * Fs[i * NN + j]);
        e[j] = v;
        s += v;
    }
    float rinv = __fdividef(1.0f, s);
    float* dst = g_fT + (size_t)t * NN2 + i;
    #pragma unroll
    for (int j = 0; j < NN; j++)
        dst[j * NN] = e[j] * rinv;
}

// ---------------------------------------------------------------------------
// Kernel C2 (grid 4000 x 64): one block per t. Loads fT[t] row into registers
// ONCE (thread i holds f[i][0..49]) and applies it to all pairs with this t,
// 4 pairs per pass from smem. Table traffic: 40MB instead of 164MB.
// ---------------------------------------------------------------------------
__global__ void kC2(const float* __restrict__ mus, float* __restrict__ Z) {
    int t = blockIdx.x;
    int cnt = g_cnt[t];
    if (cnt == 0) return;
    if (cnt > CAP) cnt = CAP;

    int i = threadIdx.x;              // 0..63, active < 50
    __shared__ float a_s[4][NN + 2];

    float freg[NN];
    float mu_i = 0.f;
    if (i < NN) {
        mu_i = mus[(size_t)t * NN + i];
        const float* fr = g_fT + (size_t)t * NN2 + i;
        #pragma unroll
        for (int j = 0; j < NN; j++) freg[j] = fr[j * NN];
    }

    for (int base = 0; base < cnt; base += 4) {
        if (i < NN) {
            #pragma unroll
            for (int k = 0; k < 4; k++) {
                int q = base + k;
                int pr = (q < cnt) ? g_slot[t * CAP + q] : 0;
                a_s[k][i] = g_xT[(size_t)pr * NN + i] - mu_i;
            }
        }
        __syncthreads();
        if (i < NN) {
            float acc0 = 0.f, acc1 = 0.f, acc2 = 0.f, acc3 = 0.f;
            #pragma unroll
            for (int j = 0; j < NN; j++) {
                float f = freg[j];
                acc0 += f * a_s[0][j];
                acc1 += f * a_s[1][j];
                acc2 += f * a_s[2][j];
                acc3 += f * a_s[3][j];
            }
            float acc[4] = {acc0, acc1, acc2, acc3};
            #pragma unroll
            for (int k = 0; k < 4; k++) {
                int q = base + k;
                if (q < cnt) {
                    int pr = g_slot[t * CAP + q];
                    int b = pr >> 5;
                    atomicAdd(&Z[b * NN + i], acc[k]);
                }
            }
        }
        __syncthreads();
    }
}

// ---------------------------------------------------------------------------
extern "C" void kernel_launch(void* const* d_in, const int* in_sizes, int n_in,
                              void* d_out, int out_size) {
    const float* x      = (const float*)d_in[0];   // [512,50,32]
    const int*   x_i    = (const int*)  d_in[1];   // [512,32]
    const int*   y_i    = (const int*)  d_in[2];   // [512]
    const float* g      = (const float*)d_in[3];   // [2500,2500]
    const float* w      = (const float*)d_in[4];   // [2500,1]
    const float* mus    = (const float*)d_in[5];   // [4000,50]
    const float* alphas = (const float*)d_in[6];   // [4000,1]

    float* Z    = (float*)d_out;        // [512*50]
    float* outF = Z + BB * NN;          // [2500]

    kA_F<<<NN2, 256>>>(g, w, outF, y_i, mus, x, Z);
    kB_softmaxT<<<ATT / 4, 256>>>(alphas, x_i);
    kC2<<<ATT, 64>>>(mus, Z);
}